// round 1
// baseline (speedup 1.0000x reference)
#include <cuda_runtime.h>
#include <cstdint>

// Problem constants
#define RB   64      // batch
#define RT   512     // time steps
#define RDI  512     // input dim
#define RH   1024    // hidden
#define RDO  512     // out dim
#define RG   128     // persistent-rec grid size (<= SM count for residency)
#define RNC  8       // columns per CTA in recurrence (RG*RNC = RH)
#define RKC  32      // K-chunk staged in smem

// ---------------- scratch (device globals; no allocation allowed) -----------
__device__ float g_pre[RT * RB * RH];     // 128 MB: pre-activations (reused for layer0/1)
__device__ float g_h1 [RT * RB * RH];     // 128 MB: layer-0 hidden outputs
__device__ float g_hbuf[2][RB * RH];      // ping-pong hidden state
__device__ unsigned int          g_bar_count = 0;
__device__ volatile unsigned int g_bar_gen   = 0;

// ---------------- software grid barrier (all RG CTAs co-resident) -----------
__device__ __forceinline__ void grid_sync() {
    __syncthreads();
    if (threadIdx.x == 0) {
        unsigned gen = g_bar_gen;
        __threadfence();
        if (atomicAdd(&g_bar_count, 1) == RG - 1) {
            g_bar_count = 0;
            __threadfence();
            g_bar_gen = gen + 1;
        } else {
            while (g_bar_gen == gen) { }
            __threadfence();
        }
    }
    __syncthreads();
}

// ---------------- GEMM: out[r][n] = sum_k A_row(r)[k] * W[n][k] + bias[n] ----
// r = t*RB + b ; A element offset = b*sA_b + t*sA_t + k ; out is [T*B][N] row-major
// M = RT*RB = 32768, N = RH = 1024, both multiples of 128. K multiple of 8.
#define BM 128
#define BN 128
#define BK 8

__global__ __launch_bounds__(256)
void gemm_bias(const float* __restrict__ A, const float* __restrict__ W,
               const float* __restrict__ bias, float* __restrict__ out,
               int K, int sA_t, int sA_b)
{
    __shared__ float As[BK][BM];
    __shared__ float Bs[BK][BN + 4];

    const int bx = blockIdx.x;   // N tile (0..7)
    const int by = blockIdx.y;   // M tile (0..255)
    const int tid = threadIdx.x;

    // A tile loader: thread -> (row = tid>>1, colgroup = (tid&1)*4)
    const int aRow = tid >> 1;
    const int aCol = (tid & 1) * 4;
    const int r    = by * BM + aRow;
    const int tt   = r >> 6;          // r / 64
    const int bb   = r & 63;          // r % 64
    const float* aPtr = A + (size_t)bb * sA_b + (size_t)tt * sA_t + aCol;

    // B (=W) tile loader: thread -> (n = tid>>1, kgroup = (tid&1)*4)
    const int bN   = tid >> 1;
    const int bCol = (tid & 1) * 4;
    const float* wPtr = W + (size_t)(bx * BN + bN) * K + bCol;

    const int ty = tid >> 4;     // 0..15
    const int tx = tid & 15;     // 0..15

    float acc[8][8];
    #pragma unroll
    for (int i = 0; i < 8; i++)
        #pragma unroll
        for (int j = 0; j < 8; j++) acc[i][j] = 0.f;

    for (int k0 = 0; k0 < K; k0 += BK) {
        float4 av = *(const float4*)(aPtr + k0);
        float4 wv = *(const float4*)(wPtr + k0);
        As[aCol + 0][aRow] = av.x;
        As[aCol + 1][aRow] = av.y;
        As[aCol + 2][aRow] = av.z;
        As[aCol + 3][aRow] = av.w;
        Bs[bCol + 0][bN] = wv.x;
        Bs[bCol + 1][bN] = wv.y;
        Bs[bCol + 2][bN] = wv.z;
        Bs[bCol + 3][bN] = wv.w;
        __syncthreads();

        #pragma unroll
        for (int kk = 0; kk < BK; kk++) {
            float a[8], bfr[8];
            *(float4*)&a[0]   = *(const float4*)&As[kk][ty * 8];
            *(float4*)&a[4]   = *(const float4*)&As[kk][ty * 8 + 4];
            *(float4*)&bfr[0] = *(const float4*)&Bs[kk][tx * 8];
            *(float4*)&bfr[4] = *(const float4*)&Bs[kk][tx * 8 + 4];
            #pragma unroll
            for (int i = 0; i < 8; i++)
                #pragma unroll
                for (int j = 0; j < 8; j++)
                    acc[i][j] = fmaf(a[i], bfr[j], acc[i][j]);
        }
        __syncthreads();
    }

    // epilogue
    float bv[8];
    #pragma unroll
    for (int j = 0; j < 8; j++) bv[j] = bias[bx * BN + tx * 8 + j];

    #pragma unroll
    for (int i = 0; i < 8; i++) {
        const int row = by * BM + ty * 8 + i;
        float* op = out + (size_t)row * RH + bx * BN + tx * 8;
        float4 v0, v1;
        v0.x = acc[i][0] + bv[0]; v0.y = acc[i][1] + bv[1];
        v0.z = acc[i][2] + bv[2]; v0.w = acc[i][3] + bv[3];
        v1.x = acc[i][4] + bv[4]; v1.y = acc[i][5] + bv[5];
        v1.z = acc[i][6] + bv[6]; v1.w = acc[i][7] + bv[7];
        *(float4*)(op)     = v0;
        *(float4*)(op + 4) = v1;
    }
}

// ---------------- persistent recurrence kernel ------------------------------
// h_t[b][n] = tanh( pre[t][b][n] + sum_k h_{t-1}[b][k]*Whh[n][k] + bhh[n] )
// 128 CTAs x 256 threads. Each CTA owns 8 columns (one per warp).
// Each thread handles b = lane and b = lane+32 for its warp's column.
__global__ __launch_bounds__(256)
void rec_kernel(const float* __restrict__ pre, const float* __restrict__ Whh,
                const float* __restrict__ bhh, float* __restrict__ h1out)
{
    __shared__ float Ws[RNC][RH];          // 32 KB: W_hh rows for this CTA's 8 cols
    __shared__ float hs[RB][RKC + 4];      // 9.2 KB: staged h chunk (padded)

    const int tid  = threadIdx.x;
    const int nq   = tid >> 5;             // warp id = local column (0..7)
    const int lane = tid & 31;
    const int ncol = blockIdx.x * RNC + nq;

    // preload W_hh slice (resident for all 512 steps)
    #pragma unroll
    for (int i = tid; i < RNC * RH / 4; i += 256) {
        const int n  = i >> 8;             // /256 float4 per row
        const int k4 = i & 255;
        ((float4*)&Ws[n][0])[k4] =
            ((const float4*)(Whh + (size_t)(blockIdx.x * RNC + n) * RH))[k4];
    }
    const float bias = bhh[ncol];

    // zero initial hidden state (hbuf[0])
    for (int i = blockIdx.x * 256 + tid; i < RB * RH; i += RG * 256)
        g_hbuf[0][i] = 0.f;

    grid_sync();

    #pragma unroll 1
    for (int t = 0; t < RT; ++t) {
        const float* hprev = g_hbuf[t & 1];
        float*       hnext = g_hbuf[(t + 1) & 1];

        float4 acc0 = {0.f, 0.f, 0.f, 0.f};
        float4 acc1 = {0.f, 0.f, 0.f, 0.f};

        #pragma unroll 1
        for (int kc = 0; kc < RH; kc += RKC) {
            // stage h[0:64][kc:kc+32]: 512 float4 over 256 threads
            #pragma unroll
            for (int i = 0; i < 2; i++) {
                const int e  = tid + i * 256;
                const int b  = e >> 3;
                const int kv = e & 7;
                float4 v = *(const float4*)(hprev + b * RH + kc + kv * 4);
                *(float4*)&hs[b][kv * 4] = v;
            }
            __syncthreads();

            #pragma unroll
            for (int kk = 0; kk < RKC; kk += 4) {
                float4 w  = *(const float4*)&Ws[nq][kc + kk];
                float4 h0 = *(const float4*)&hs[lane][kk];
                float4 h1 = *(const float4*)&hs[lane + 32][kk];
                acc0.x = fmaf(h0.x, w.x, acc0.x);
                acc0.y = fmaf(h0.y, w.y, acc0.y);
                acc0.z = fmaf(h0.z, w.z, acc0.z);
                acc0.w = fmaf(h0.w, w.w, acc0.w);
                acc1.x = fmaf(h1.x, w.x, acc1.x);
                acc1.y = fmaf(h1.y, w.y, acc1.y);
                acc1.z = fmaf(h1.z, w.z, acc1.z);
                acc1.w = fmaf(h1.w, w.w, acc1.w);
            }
            __syncthreads();
        }

        const float a0 = (acc0.x + acc0.y) + (acc0.z + acc0.w);
        const float a1 = (acc1.x + acc1.y) + (acc1.z + acc1.w);

        const float* pt = pre + (size_t)t * (RB * RH);
        const float v0 = tanhf(pt[lane * RH + ncol] + a0 + bias);
        const float v1 = tanhf(pt[(lane + 32) * RH + ncol] + a1 + bias);

        hnext[lane * RH + ncol]        = v0;
        hnext[(lane + 32) * RH + ncol] = v1;
        if (h1out) {
            float* o = h1out + (size_t)t * (RB * RH);
            o[lane * RH + ncol]        = v0;
            o[(lane + 32) * RH + ncol] = v1;
        }
        grid_sync();
    }
}

// ---------------- FC head: out[b][o] = h[b] . Wfc[o] + bfc[o] ----------------
__global__ __launch_bounds__(256)
void fc_kernel(const float* __restrict__ h, const float* __restrict__ Wfc,
               const float* __restrict__ bfc, float* __restrict__ out)
{
    const int w    = (blockIdx.x * blockDim.x + threadIdx.x) >> 5;
    const int lane = threadIdx.x & 31;
    if (w >= RB * RDO) return;
    const int b = w >> 9;        // / RDO
    const int o = w & (RDO - 1);

    const float* hp = h   + (size_t)b * RH;
    const float* wp = Wfc + (size_t)o * RH;
    float acc = 0.f;
    #pragma unroll
    for (int k = lane * 4; k < RH; k += 128) {
        float4 hv = *(const float4*)(hp + k);
        float4 wv = *(const float4*)(wp + k);
        acc += hv.x * wv.x + hv.y * wv.y + hv.z * wv.z + hv.w * wv.w;
    }
    #pragma unroll
    for (int s = 16; s > 0; s >>= 1) acc += __shfl_xor_sync(0xffffffffu, acc, s);
    if (lane == 0) out[w] = acc + bfc[o];
}

// ---------------- launch ----------------------------------------------------
extern "C" void kernel_launch(void* const* d_in, const int* in_sizes, int n_in,
                              void* d_out, int out_size)
{
    const float* x     = (const float*)d_in[0];
    const float* W_ih0 = (const float*)d_in[1];
    const float* W_hh0 = (const float*)d_in[2];
    const float* b_ih0 = (const float*)d_in[3];
    const float* b_hh0 = (const float*)d_in[4];
    const float* W_ih1 = (const float*)d_in[5];
    const float* W_hh1 = (const float*)d_in[6];
    const float* b_ih1 = (const float*)d_in[7];
    const float* b_hh1 = (const float*)d_in[8];
    const float* W_fc  = (const float*)d_in[9];
    const float* b_fc  = (const float*)d_in[10];

    float *pre, *h1, *hbuf;
    cudaGetSymbolAddress((void**)&pre,  g_pre);
    cudaGetSymbolAddress((void**)&h1,   g_h1);
    cudaGetSymbolAddress((void**)&hbuf, g_hbuf);

    dim3 ggrid(RH / BN, (RT * RB) / BM);   // (8, 256)

    // pre0 = x @ W_ih0^T + b_ih0   (A = x[b][t][d]: off = b*T*DI + t*DI)
    gemm_bias<<<ggrid, 256>>>(x, W_ih0, b_ih0, pre, RDI, RDI, RT * RDI);
    // layer-0 recurrence, store all h1[t]
    rec_kernel<<<RG, 256>>>(pre, W_hh0, b_hh0, h1);
    // pre1 = h1 @ W_ih1^T + b_ih1  (A = h1[t][b][h]: off = t*B*H + b*H)
    gemm_bias<<<ggrid, 256>>>(h1, W_ih1, b_ih1, pre, RH, RB * RH, RH);
    // layer-1 recurrence (only final state needed; lands in g_hbuf[0] since T even)
    rec_kernel<<<RG, 256>>>(pre, W_hh1, b_hh1, nullptr);
    // FC head
    fc_kernel<<<(RB * RDO) / 8, 256>>>(hbuf, W_fc, b_fc, (float*)d_out);
}

// round 2
// speedup vs baseline: 1.7259x; 1.7259x over previous
#include <cuda_runtime.h>
#include <mma.h>
#include <cstdint>

using namespace nvcuda;

// ---------------- problem constants -----------------------------------------
#define RB   64      // batch
#define RT   512     // time steps
#define RDI  512     // input dim
#define RH   1024    // hidden
#define RDO  512     // out dim

// ---------------- GEMM tiling ------------------------------------------------
#define BM   128
#define BN   64
#define BK   32
#define LDA  36      // BK + 4 pad
#define LDB  36

// ---------------- recurrence tiling ------------------------------------------
#define RG2  64      // persistent CTAs (<= SM count, residency guaranteed)
#define NC2  16      // hidden columns per CTA (RG2*NC2 = RH)
#define KS   64      // k-chunk staged per iteration
#define LDH  68      // KS + 4 pad
#define LDW  1032    // RH + 8 pad
#define REC_SMEM_FLOATS (NC2*LDW + 2*RB*LDH + 2048 + NC2)
#define REC_SMEM_BYTES  (REC_SMEM_FLOATS * 4)

// ---------------- scratch (device globals; no allocation allowed) ------------
__device__ float g_pre[RT * RB * RH];     // 128 MB pre-activations (layer0 then layer1)
__device__ float g_h1 [RT * RB * RH];     // 128 MB layer-0 hidden outputs
__device__ float g_hbuf[2][RB * RH];      // ping-pong hidden state
__device__ unsigned int          g_bar_count = 0;
__device__ volatile unsigned int g_bar_gen   = 0;

// ---------------- helpers -----------------------------------------------------
__device__ __forceinline__ float to_tf32(float x) {
    float r;
    asm("cvt.rna.tf32.f32 %0, %1;" : "=f"(r) : "f"(x));
    return r;
}

__device__ __forceinline__ void grid_sync(unsigned ncta) {
    __syncthreads();
    if (threadIdx.x == 0) {
        unsigned gen = g_bar_gen;
        __threadfence();
        if (atomicAdd(&g_bar_count, 1) == ncta - 1) {
            g_bar_count = 0;
            __threadfence();
            g_bar_gen = gen + 1;
        } else {
            while (g_bar_gen == gen) { }
            __threadfence();
        }
    }
    __syncthreads();
}

// ---------------- TF32 GEMM: out[r][n] = sum_k A_row(r)[k] * W[n][k] ----------
// r = t*RB + b ; A element offset = b*sA_b + t*sA_t + k ; out row-major ld=RH.
// No bias (biases are folded into the recurrence kernel).
__global__ __launch_bounds__(256)
void gemm_tf32(const float* __restrict__ A, const float* __restrict__ W,
               float* __restrict__ out, int K, int sA_t, int sA_b)
{
    __shared__ float As[BM * LDA];
    __shared__ float Bs[BN * LDB];

    const int tid = threadIdx.x;
    const int wid = tid >> 5;
    const int wm  = wid >> 1;        // 0..3 -> M offset wm*32
    const int wn  = wid & 1;         // 0..1 -> N offset wn*32
    const int bx  = blockIdx.x;      // N tile
    const int by  = blockIdx.y;      // M tile

    wmma::fragment<wmma::accumulator, 16, 16, 8, float> c[2][2];
    #pragma unroll
    for (int i = 0; i < 2; i++)
        #pragma unroll
        for (int j = 0; j < 2; j++) wmma::fill_fragment(c[i][j], 0.0f);

    for (int k0 = 0; k0 < K; k0 += BK) {
        // A tile: 128x32 = 1024 float4, 4 per thread
        #pragma unroll
        for (int p = 0; p < 4; p++) {
            const int i   = tid + p * 256;
            const int row = i >> 3;
            const int c4  = i & 7;
            const int r   = by * BM + row;
            const int tt  = r >> 6;
            const int bb  = r & 63;
            float4 v = *(const float4*)(A + (size_t)bb * sA_b + (size_t)tt * sA_t + k0 + c4 * 4);
            float* d = &As[row * LDA + c4 * 4];
            d[0] = to_tf32(v.x); d[1] = to_tf32(v.y);
            d[2] = to_tf32(v.z); d[3] = to_tf32(v.w);
        }
        // B tile: 64x32 = 512 float4, 2 per thread
        #pragma unroll
        for (int p = 0; p < 2; p++) {
            const int i  = tid + p * 256;
            const int n  = i >> 3;
            const int c4 = i & 7;
            float4 v = *(const float4*)(W + (size_t)(bx * BN + n) * K + k0 + c4 * 4);
            float* d = &Bs[n * LDB + c4 * 4];
            d[0] = to_tf32(v.x); d[1] = to_tf32(v.y);
            d[2] = to_tf32(v.z); d[3] = to_tf32(v.w);
        }
        __syncthreads();

        #pragma unroll
        for (int s = 0; s < 4; s++) {
            wmma::fragment<wmma::matrix_a, 16, 16, 8, wmma::precision::tf32, wmma::row_major> a0, a1;
            wmma::fragment<wmma::matrix_b, 16, 16, 8, wmma::precision::tf32, wmma::col_major> b0, b1;
            wmma::load_matrix_sync(a0, &As[(wm * 32)      * LDA + s * 8], LDA);
            wmma::load_matrix_sync(a1, &As[(wm * 32 + 16) * LDA + s * 8], LDA);
            wmma::load_matrix_sync(b0, &Bs[(wn * 32)      * LDB + s * 8], LDB);
            wmma::load_matrix_sync(b1, &Bs[(wn * 32 + 16) * LDB + s * 8], LDB);
            wmma::mma_sync(c[0][0], a0, b0, c[0][0]);
            wmma::mma_sync(c[0][1], a0, b1, c[0][1]);
            wmma::mma_sync(c[1][0], a1, b0, c[1][0]);
            wmma::mma_sync(c[1][1], a1, b1, c[1][1]);
        }
        __syncthreads();
    }

    #pragma unroll
    for (int i = 0; i < 2; i++)
        #pragma unroll
        for (int j = 0; j < 2; j++) {
            const int r  = by * BM + wm * 32 + i * 16;
            const int cc = bx * BN + wn * 32 + j * 16;
            wmma::store_matrix_sync(out + (size_t)r * RH + cc, c[i][j], RH, wmma::mem_row_major);
        }
}

// ---------------- persistent TF32 recurrence ---------------------------------
// h_t[b][n] = tanh( pre[t][b][n] + sum_k h_{t-1}[b][k]*Whh[n][k] + b_ih[n] + b_hh[n] )
// 64 CTAs x 256 threads. CTA owns 16 columns. 8 warps = 4 M-tiles x 2 K-splits.
__global__ __launch_bounds__(256)
void rec_tf32(const float* __restrict__ pre, const float* __restrict__ Whh,
              const float* __restrict__ b_ih, const float* __restrict__ b_hh,
              float* __restrict__ h1out)
{
    extern __shared__ float sm[];
    float* Ws    = sm;                        // NC2 * LDW  (W_hh rows, tf32-rounded)
    float* hs    = Ws + NC2 * LDW;            // 2 * RB * LDH (double-buffered h chunk)
    float* rs    = hs + 2 * RB * LDH;         // 2 * 4 * 16 * 16 (k-split partials)
    float* sbias = rs + 2048;                 // NC2

    const int tid   = threadIdx.x;
    const int wid   = tid >> 5;
    const int mw    = wid >> 1;               // 0..3 -> rows mw*16
    const int kw    = wid & 1;                // 0..1 -> K half
    const int ncol0 = blockIdx.x * NC2;

    // resident W_hh slice (tf32-rounded): 16 x 1024 = 4096 float4
    for (int i = tid; i < NC2 * RH / 4; i += 256) {
        const int n  = i >> 8;
        const int c4 = i & 255;
        float4 v = *(const float4*)(Whh + (size_t)(ncol0 + n) * RH + c4 * 4);
        float* d = &Ws[n * LDW + c4 * 4];
        d[0] = to_tf32(v.x); d[1] = to_tf32(v.y);
        d[2] = to_tf32(v.z); d[3] = to_tf32(v.w);
    }
    if (tid < NC2) sbias[tid] = b_ih[ncol0 + tid] + b_hh[ncol0 + tid];

    // zero initial hidden state
    for (int i = blockIdx.x * 256 + tid; i < RB * RH; i += RG2 * 256)
        g_hbuf[0][i] = 0.0f;

    grid_sync(RG2);

    #pragma unroll 1
    for (int t = 0; t < RT; ++t) {
        const float* hprev = g_hbuf[t & 1];
        float*       hnext = g_hbuf[(t + 1) & 1];

        wmma::fragment<wmma::accumulator, 16, 16, 8, float> cf;
        wmma::fill_fragment(cf, 0.0f);

        // prologue: stage chunk 0 (64x64 = 1024 float4, 4/thread)
        float4 pf[4];
        #pragma unroll
        for (int p = 0; p < 4; p++) {
            const int i = tid + p * 256;
            pf[p] = *(const float4*)(hprev + (i >> 4) * RH + (i & 15) * 4);
        }
        #pragma unroll
        for (int p = 0; p < 4; p++) {
            const int i = tid + p * 256;
            float* d = &hs[(i >> 4) * LDH + (i & 15) * 4];
            d[0] = to_tf32(pf[p].x); d[1] = to_tf32(pf[p].y);
            d[2] = to_tf32(pf[p].z); d[3] = to_tf32(pf[p].w);
        }
        __syncthreads();

        #pragma unroll 1
        for (int c = 0; c < RH / KS; ++c) {
            // prefetch next chunk into registers (overlaps with mma below)
            if (c < RH / KS - 1) {
                #pragma unroll
                for (int p = 0; p < 4; p++) {
                    const int i = tid + p * 256;
                    pf[p] = *(const float4*)(hprev + (i >> 4) * RH + (c + 1) * KS + (i & 15) * 4);
                }
            }
            const float* hb = &hs[(c & 1) * RB * LDH];
            #pragma unroll
            for (int s = 0; s < 4; s++) {
                const int kloc = kw * 32 + s * 8;
                wmma::fragment<wmma::matrix_a, 16, 16, 8, wmma::precision::tf32, wmma::row_major> af;
                wmma::fragment<wmma::matrix_b, 16, 16, 8, wmma::precision::tf32, wmma::col_major> bf;
                wmma::load_matrix_sync(af, hb + (mw * 16) * LDH + kloc, LDH);
                wmma::load_matrix_sync(bf, Ws + c * KS + kloc, LDW);
                wmma::mma_sync(cf, af, bf, cf);
            }
            __syncthreads();
            if (c < RH / KS - 1) {
                float* d0 = &hs[((c + 1) & 1) * RB * LDH];
                #pragma unroll
                for (int p = 0; p < 4; p++) {
                    const int i = tid + p * 256;
                    float* d = d0 + (i >> 4) * LDH + (i & 15) * 4;
                    d[0] = to_tf32(pf[p].x); d[1] = to_tf32(pf[p].y);
                    d[2] = to_tf32(pf[p].z); d[3] = to_tf32(pf[p].w);
                }
                __syncthreads();
            }
        }

        // k-split reduction + activation
        wmma::store_matrix_sync(&rs[(kw * 4 + mw) * 256], cf, 16, wmma::mem_row_major);
        __syncthreads();
        {
            const int id  = tid * 4;          // 4 consecutive n per thread
            const int b   = id >> 4;
            const int n   = id & 15;
            const int mwb = b >> 4;
            const int br  = b & 15;
            float4 r0 = *(float4*)&rs[(0 * 4 + mwb) * 256 + br * 16 + n];
            float4 r1 = *(float4*)&rs[(1 * 4 + mwb) * 256 + br * 16 + n];
            float4 pv = *(const float4*)(pre + (size_t)t * (RB * RH) + b * RH + ncol0 + n);
            float4 o;
            o.x = tanhf(pv.x + r0.x + r1.x + sbias[n + 0]);
            o.y = tanhf(pv.y + r0.y + r1.y + sbias[n + 1]);
            o.z = tanhf(pv.z + r0.z + r1.z + sbias[n + 2]);
            o.w = tanhf(pv.w + r0.w + r1.w + sbias[n + 3]);
            *(float4*)(hnext + b * RH + ncol0 + n) = o;
            if (h1out)
                *(float4*)(h1out + (size_t)t * (RB * RH) + b * RH + ncol0 + n) = o;
        }
        grid_sync(RG2);
    }
}

// ---------------- FC head: out[b][o] = h[b] . Wfc[o] + bfc[o] (fp32) ----------
__global__ __launch_bounds__(256)
void fc_kernel(const float* __restrict__ h, const float* __restrict__ Wfc,
               const float* __restrict__ bfc, float* __restrict__ out)
{
    const int w    = (blockIdx.x * blockDim.x + threadIdx.x) >> 5;
    const int lane = threadIdx.x & 31;
    if (w >= RB * RDO) return;
    const int b = w >> 9;
    const int o = w & (RDO - 1);

    const float* hp = h   + (size_t)b * RH;
    const float* wp = Wfc + (size_t)o * RH;
    float acc = 0.f;
    #pragma unroll
    for (int k = lane * 4; k < RH; k += 128) {
        float4 hv = *(const float4*)(hp + k);
        float4 wv = *(const float4*)(wp + k);
        acc += hv.x * wv.x + hv.y * wv.y + hv.z * wv.z + hv.w * wv.w;
    }
    #pragma unroll
    for (int s = 16; s > 0; s >>= 1) acc += __shfl_xor_sync(0xffffffffu, acc, s);
    if (lane == 0) out[w] = acc + bfc[o];
}

// ---------------- launch ------------------------------------------------------
extern "C" void kernel_launch(void* const* d_in, const int* in_sizes, int n_in,
                              void* d_out, int out_size)
{
    const float* x     = (const float*)d_in[0];
    const float* W_ih0 = (const float*)d_in[1];
    const float* W_hh0 = (const float*)d_in[2];
    const float* b_ih0 = (const float*)d_in[3];
    const float* b_hh0 = (const float*)d_in[4];
    const float* W_ih1 = (const float*)d_in[5];
    const float* W_hh1 = (const float*)d_in[6];
    const float* b_ih1 = (const float*)d_in[7];
    const float* b_hh1 = (const float*)d_in[8];
    const float* W_fc  = (const float*)d_in[9];
    const float* b_fc  = (const float*)d_in[10];

    float *pre, *h1, *hbuf;
    cudaGetSymbolAddress((void**)&pre,  g_pre);
    cudaGetSymbolAddress((void**)&h1,   g_h1);
    cudaGetSymbolAddress((void**)&hbuf, g_hbuf);

    cudaFuncSetAttribute(rec_tf32, cudaFuncAttributeMaxDynamicSharedMemorySize, REC_SMEM_BYTES);

    dim3 ggrid(RH / BN, (RT * RB) / BM);   // (16, 256)

    // pre0 = x @ W_ih0^T           (x[b][t][d]: sA_t = RDI, sA_b = RT*RDI)
    gemm_tf32<<<ggrid, 256>>>(x, W_ih0, pre, RDI, RDI, RT * RDI);
    // layer-0 recurrence (stores all h1[t]); biases b_ih0+b_hh0 fused here
    rec_tf32<<<RG2, 256, REC_SMEM_BYTES>>>(pre, W_hh0, b_ih0, b_hh0, h1);
    // pre1 = h1 @ W_ih1^T          (h1[t][b][h]: sA_t = RB*RH, sA_b = RH)
    gemm_tf32<<<ggrid, 256>>>(h1, W_ih1, pre, RH, RB * RH, RH);
    // layer-1 recurrence (final state lands in g_hbuf[0] since RT is even)
    rec_tf32<<<RG2, 256, REC_SMEM_BYTES>>>(pre, W_hh1, b_ih1, b_hh1, nullptr);
    // FC head in fp32
    fc_kernel<<<(RB * RDO) / 8, 256>>>(hbuf, W_fc, b_fc, (float*)d_out);
}

// round 3
// speedup vs baseline: 1.7471x; 1.0123x over previous
#include <cuda_runtime.h>
#include <mma.h>
#include <cstdint>

using namespace nvcuda;

// ---------------- problem constants -----------------------------------------
#define RB   64
#define RT   512
#define RDI  512
#define RH   1024
#define RDO  512

// ---------------- GEMM tiling -------------------------------------------------
#define GBM 128
#define GBN 128
#define GBK 32
#define GLD 36                               // GBK + 4 pad
#define GEMM_SMEM_BYTES (2 * (GBM * GLD + GBN * GLD) * 4)

// ---------------- recurrence tiling -------------------------------------------
#define RG2  64      // persistent CTAs
#define NC2  16      // hidden columns per CTA
#define KS   128     // k-chunk per pipeline stage
#define NCH  (RH / KS)                       // 8 chunks
#define LDH  132                             // KS + 4
#define LDW  1032                            // RH + 8
#define REC_SMEM_BYTES ((NC2 * LDW + 2 * RB * LDH + 2048 + NC2) * 4)

// ---------------- scratch ------------------------------------------------------
__device__ float    g_pre[RT * RB * RH];     // pre-activations
__device__ float    g_h1 [RT * RB * RH];     // hidden-state history (both layers)
__device__ unsigned g_flags[2 * RG2];        // per-CTA published-step counters

// ---------------- helpers ------------------------------------------------------
__device__ __forceinline__ float to_tf32(float x) {
    float r;
    asm("cvt.rna.tf32.f32 %0, %1;" : "=f"(r) : "f"(x));
    return r;
}
__device__ __forceinline__ unsigned ld_acq(const unsigned* p) {
    unsigned v;
    asm volatile("ld.acquire.gpu.u32 %0, [%1];" : "=r"(v) : "l"(p) : "memory");
    return v;
}
__device__ __forceinline__ void st_rel(unsigned* p, unsigned v) {
    asm volatile("st.release.gpu.u32 [%0], %1;" :: "l"(p), "r"(v) : "memory");
}

// ---------------- TF32 GEMM: out[r][n] = sum_k A_row(r)[k] * W[n][k] -----------
// r = t*RB + b ; A element offset = b*sA_b + t*sA_t + k ; out row-major ld=RH.
__global__ __launch_bounds__(256)
void gemm_tf32(const float* __restrict__ A, const float* __restrict__ W,
               float* __restrict__ out, int K, int sA_t, int sA_b)
{
    extern __shared__ float sm[];
    float* As = sm;                          // 2 * GBM*GLD
    float* Bs = sm + 2 * GBM * GLD;          // 2 * GBN*GLD

    const int tid = threadIdx.x;
    const int wid = tid >> 5;
    const int wm  = wid & 1;                 // m-half (64 rows)
    const int wn  = wid >> 1;                // n-quarter (32 cols)
    const int bx  = blockIdx.x;
    const int by  = blockIdx.y;

    // loader geometry: each thread owns one tile-row half (16 floats)
    const int lRow = tid >> 1;
    const int lC   = (tid & 1) * 16;
    const int r    = by * GBM + lRow;
    const int tt   = r >> 6;
    const int bb   = r & 63;
    const float* aPtr = A + (size_t)bb * sA_b + (size_t)tt * sA_t + lC;
    const float* wPtr = W + (size_t)(bx * GBN + lRow) * K + lC;

    wmma::fragment<wmma::accumulator, 16, 16, 8, float> acc[4][2];
    #pragma unroll
    for (int i = 0; i < 4; i++)
        #pragma unroll
        for (int j = 0; j < 2; j++) wmma::fill_fragment(acc[i][j], 0.0f);

    float4 ra[4], rb[4];
    #pragma unroll
    for (int p = 0; p < 4; p++) {
        ra[p] = *(const float4*)(aPtr + p * 4);
        rb[p] = *(const float4*)(wPtr + p * 4);
    }

    const int niter = K / GBK;
    for (int c = 0; c < niter; c++) {
        // store staged regs (chunk c) with RNA tf32 rounding
        {
            float* dA = As + (c & 1) * GBM * GLD + lRow * GLD + lC;
            float* dB = Bs + (c & 1) * GBN * GLD + lRow * GLD + lC;
            #pragma unroll
            for (int p = 0; p < 4; p++) {
                dA[p * 4 + 0] = to_tf32(ra[p].x); dA[p * 4 + 1] = to_tf32(ra[p].y);
                dA[p * 4 + 2] = to_tf32(ra[p].z); dA[p * 4 + 3] = to_tf32(ra[p].w);
                dB[p * 4 + 0] = to_tf32(rb[p].x); dB[p * 4 + 1] = to_tf32(rb[p].y);
                dB[p * 4 + 2] = to_tf32(rb[p].z); dB[p * 4 + 3] = to_tf32(rb[p].w);
            }
        }
        if (c + 1 < niter) {
            const float* a2 = aPtr + (c + 1) * GBK;
            const float* w2 = wPtr + (c + 1) * GBK;
            #pragma unroll
            for (int p = 0; p < 4; p++) {
                ra[p] = *(const float4*)(a2 + p * 4);
                rb[p] = *(const float4*)(w2 + p * 4);
            }
        }
        __syncthreads();

        const float* bufA = As + (c & 1) * GBM * GLD;
        const float* bufB = Bs + (c & 1) * GBN * GLD;
        #pragma unroll
        for (int s = 0; s < 4; s++) {
            wmma::fragment<wmma::matrix_a, 16, 16, 8, wmma::precision::tf32, wmma::row_major> af[4];
            wmma::fragment<wmma::matrix_b, 16, 16, 8, wmma::precision::tf32, wmma::col_major> bf[2];
            #pragma unroll
            for (int i = 0; i < 4; i++)
                wmma::load_matrix_sync(af[i], bufA + (wm * 64 + i * 16) * GLD + s * 8, GLD);
            #pragma unroll
            for (int j = 0; j < 2; j++)
                wmma::load_matrix_sync(bf[j], bufB + (wn * 32 + j * 16) * GLD + s * 8, GLD);
            #pragma unroll
            for (int i = 0; i < 4; i++)
                #pragma unroll
                for (int j = 0; j < 2; j++)
                    wmma::mma_sync(acc[i][j], af[i], bf[j], acc[i][j]);
        }
    }

    #pragma unroll
    for (int i = 0; i < 4; i++)
        #pragma unroll
        for (int j = 0; j < 2; j++) {
            const int rr = by * GBM + wm * 64 + i * 16;
            const int cc = bx * GBN + wn * 32 + j * 16;
            wmma::store_matrix_sync(out + (size_t)rr * RH + cc, acc[i][j], RH, wmma::mem_row_major);
        }
}

// ---------------- persistent recurrence (flag-pipelined, no grid barrier) ------
// h_t[b][n] = tanh( pre[t][b][n] + sum_k h_{t-1}[b][k]*Whh[n][k] + b_ih[n]+b_hh[n] )
// hist holds every h_t; flags[cta] = number of steps that CTA has published.
__global__ __launch_bounds__(256)
void rec_tf32(const float* __restrict__ pre, const float* __restrict__ Whh,
              const float* __restrict__ b_ih, const float* __restrict__ b_hh,
              float* __restrict__ hist, unsigned* __restrict__ flags)
{
    extern __shared__ float sm[];
    float* Ws    = sm;                       // NC2 * LDW
    float* hs    = Ws + NC2 * LDW;           // 2 * RB * LDH
    float* rs    = hs + 2 * RB * LDH;        // 2048
    float* sbias = rs + 2048;                // NC2

    const int tid   = threadIdx.x;
    const int wid   = tid >> 5;
    const int mw    = wid >> 1;              // m-tile (16 batch rows)
    const int kw    = wid & 1;               // k half
    const int ncol0 = blockIdx.x * NC2;

    // resident W_hh slice (tf32-rounded)
    for (int i = tid; i < NC2 * RH / 4; i += 256) {
        const int n  = i >> 8;
        const int c4 = i & 255;
        float4 v = *(const float4*)(Whh + (size_t)(ncol0 + n) * RH + c4 * 4);
        float* d = &Ws[n * LDW + c4 * 4];
        d[0] = to_tf32(v.x); d[1] = to_tf32(v.y);
        d[2] = to_tf32(v.z); d[3] = to_tf32(v.w);
    }
    if (tid < NC2) sbias[tid] = b_ih[ncol0 + tid] + b_hh[ncol0 + tid];
    __syncthreads();

    // prefetch geometry: each thread touches rows (prow + p*8), float4-col pcol4.
    // its k-columns belong to exactly one producer CTA per chunk.
    const int prow  = tid >> 5;              // 0..7
    const int pcol4 = tid & 31;              // 0..31
    const int pprod = pcol4 >> 2;            // 0..7 producer-within-chunk

    // epilogue geometry: one float4 per thread
    const int eb = tid >> 2;                 // batch row 0..63
    const int en = (tid & 3) * 4;            // col within NC2

    #pragma unroll 1
    for (int t = 0; t < RT; ++t) {
        float a0 = 0.f, a1 = 0.f, a2 = 0.f, a3 = 0.f;

        if (t > 0) {
            const float* hprev = hist + (size_t)(t - 1) * (RB * RH);

            // wait + prefetch chunk 0 (each thread waits only on ITS producer)
            {
                const unsigned* f = &flags[0 * (KS / NC2) + pprod];
                while (ld_acq(f) < (unsigned)t) { }
            }
            float4 pf[8];
            #pragma unroll
            for (int p = 0; p < 8; p++)
                pf[p] = *(const float4*)(hprev + (prow + p * 8) * RH + pcol4 * 4);

            wmma::fragment<wmma::accumulator, 16, 16, 8, float> cf;
            wmma::fill_fragment(cf, 0.0f);

            #pragma unroll 1
            for (int c = 0; c < NCH; ++c) {
                // stage chunk c from regs
                float* dst = hs + (c & 1) * RB * LDH;
                #pragma unroll
                for (int p = 0; p < 8; p++) {
                    float* d = dst + (prow + p * 8) * LDH + pcol4 * 4;
                    d[0] = to_tf32(pf[p].x); d[1] = to_tf32(pf[p].y);
                    d[2] = to_tf32(pf[p].z); d[3] = to_tf32(pf[p].w);
                }
                // wait + prefetch chunk c+1
                if (c + 1 < NCH) {
                    const unsigned* f = &flags[(c + 1) * (KS / NC2) + pprod];
                    while (ld_acq(f) < (unsigned)t) { }
                    #pragma unroll
                    for (int p = 0; p < 8; p++)
                        pf[p] = *(const float4*)(hprev + (prow + p * 8) * RH
                                                 + (c + 1) * KS + pcol4 * 4);
                }
                __syncthreads();

                const float* hb = hs + (c & 1) * RB * LDH;
                #pragma unroll
                for (int s = 0; s < 8; s++) {
                    const int kloc = kw * 64 + s * 8;
                    wmma::fragment<wmma::matrix_a, 16, 16, 8, wmma::precision::tf32, wmma::row_major> af;
                    wmma::fragment<wmma::matrix_b, 16, 16, 8, wmma::precision::tf32, wmma::col_major> bf;
                    wmma::load_matrix_sync(af, hb + (mw * 16) * LDH + kloc, LDH);
                    wmma::load_matrix_sync(bf, Ws + c * KS + kloc, LDW);
                    wmma::mma_sync(cf, af, bf, cf);
                }
            }

            wmma::store_matrix_sync(&rs[(kw * 4 + mw) * 256], cf, 16, wmma::mem_row_major);
            __syncthreads();

            const int mwb = eb >> 4;
            const int br  = eb & 15;
            float4 r0 = *(float4*)&rs[(0 * 4 + mwb) * 256 + br * 16 + en];
            float4 r1 = *(float4*)&rs[(1 * 4 + mwb) * 256 + br * 16 + en];
            a0 = r0.x + r1.x; a1 = r0.y + r1.y;
            a2 = r0.z + r1.z; a3 = r0.w + r1.w;
        }

        // epilogue: activation + publish
        {
            float4 pv = *(const float4*)(pre + (size_t)t * (RB * RH) + eb * RH + ncol0 + en);
            float4 o;
            o.x = tanhf(pv.x + a0 + sbias[en + 0]);
            o.y = tanhf(pv.y + a1 + sbias[en + 1]);
            o.z = tanhf(pv.z + a2 + sbias[en + 2]);
            o.w = tanhf(pv.w + a3 + sbias[en + 3]);
            *(float4*)(hist + (size_t)t * (RB * RH) + eb * RH + ncol0 + en) = o;
        }
        __threadfence();
        __syncthreads();
        if (tid == 0) st_rel(&flags[blockIdx.x], (unsigned)(t + 1));
    }
}

// ---------------- FC head ------------------------------------------------------
__global__ __launch_bounds__(256)
void fc_kernel(const float* __restrict__ h, const float* __restrict__ Wfc,
               const float* __restrict__ bfc, float* __restrict__ out)
{
    const int w    = (blockIdx.x * blockDim.x + threadIdx.x) >> 5;
    const int lane = threadIdx.x & 31;
    if (w >= RB * RDO) return;
    const int b = w >> 9;
    const int o = w & (RDO - 1);

    const float* hp = h   + (size_t)b * RH;
    const float* wp = Wfc + (size_t)o * RH;
    float acc = 0.f;
    #pragma unroll
    for (int k = lane * 4; k < RH; k += 128) {
        float4 hv = *(const float4*)(hp + k);
        float4 wv = *(const float4*)(wp + k);
        acc += hv.x * wv.x + hv.y * wv.y + hv.z * wv.z + hv.w * wv.w;
    }
    #pragma unroll
    for (int s = 16; s > 0; s >>= 1) acc += __shfl_xor_sync(0xffffffffu, acc, s);
    if (lane == 0) out[w] = acc + bfc[o];
}

// ---------------- launch -------------------------------------------------------
extern "C" void kernel_launch(void* const* d_in, const int* in_sizes, int n_in,
                              void* d_out, int out_size)
{
    const float* x     = (const float*)d_in[0];
    const float* W_ih0 = (const float*)d_in[1];
    const float* W_hh0 = (const float*)d_in[2];
    const float* b_ih0 = (const float*)d_in[3];
    const float* b_hh0 = (const float*)d_in[4];
    const float* W_ih1 = (const float*)d_in[5];
    const float* W_hh1 = (const float*)d_in[6];
    const float* b_ih1 = (const float*)d_in[7];
    const float* b_hh1 = (const float*)d_in[8];
    const float* W_fc  = (const float*)d_in[9];
    const float* b_fc  = (const float*)d_in[10];

    float *pre, *hist;
    unsigned* flags;
    cudaGetSymbolAddress((void**)&pre,   g_pre);
    cudaGetSymbolAddress((void**)&hist,  g_h1);
    cudaGetSymbolAddress((void**)&flags, g_flags);

    cudaFuncSetAttribute(gemm_tf32, cudaFuncAttributeMaxDynamicSharedMemorySize, GEMM_SMEM_BYTES);
    cudaFuncSetAttribute(rec_tf32,  cudaFuncAttributeMaxDynamicSharedMemorySize, REC_SMEM_BYTES);

    // reset flags for this invocation (async memset is graph-capturable)
    cudaMemsetAsync(flags, 0, 2 * RG2 * sizeof(unsigned), 0);

    dim3 ggrid(RH / GBN, (RT * RB) / GBM);   // (8, 256)

    // pre0 = x @ W_ih0^T     (x[b][t][d]: sA_t = RDI, sA_b = RT*RDI)
    gemm_tf32<<<ggrid, 256, GEMM_SMEM_BYTES>>>(x, W_ih0, pre, RDI, RDI, RT * RDI);
    // layer-0 recurrence -> hist (g_h1)
    rec_tf32<<<RG2, 256, REC_SMEM_BYTES>>>(pre, W_hh0, b_ih0, b_hh0, hist, flags);
    // pre1 = h1 @ W_ih1^T    (hist[t][b][h]: sA_t = RB*RH, sA_b = RH)
    gemm_tf32<<<ggrid, 256, GEMM_SMEM_BYTES>>>(hist, W_ih1, pre, RH, RB * RH, RH);
    // layer-1 recurrence -> hist (reuse; layer-0 history already consumed)
    rec_tf32<<<RG2, 256, REC_SMEM_BYTES>>>(pre, W_hh1, b_ih1, b_hh1, hist, flags + RG2);
    // FC head on final hidden state
    fc_kernel<<<(RB * RDO) / 8, 256>>>(hist + (size_t)(RT - 1) * (RB * RH),
                                       W_fc, b_fc, (float*)d_out);
}

// round 4
// speedup vs baseline: 4.1696x; 2.3865x over previous
#include <cuda_runtime.h>
#include <cuda_fp16.h>
#include <mma.h>
#include <cstdint>

using namespace nvcuda;

// ---------------- problem constants -----------------------------------------
#define RB   64
#define RT   512
#define RDI  512
#define RH   1024
#define RDO  512
#define BH   (RB * RH)

// ---------------- rec tiling --------------------------------------------------
#define KC    256                    // k-chunk (halves)
#define LDHs  264                    // KC + 8 (halves)
#define LDWs  1032                   // RH + 8 (halves)
#define L0_CTAS 32
#define L1_CTAS 64
#define REC_SMEM_BYTES 150272

// ---------------- GEMM tiling (pre0 only) -------------------------------------
#define GBM 128
#define GBN 128
#define GBK 32
#define GLD 36
#define GEMM_SMEM_BYTES (2 * (GBM * GLD + GBN * GLD) * 4)

// ---------------- scratch ------------------------------------------------------
__device__ float    g_pre[RT * BH];      // fp32 pre-activations (layer 0)
__device__ __half   g_h1h[RT * BH];      // layer-0 hidden history (fp16)
__device__ __half   g_h2h[RT * BH];      // layer-1 hidden history (fp16)
__device__ unsigned g_cnt[2];            // per-layer step counters

// ---------------- helpers ------------------------------------------------------
__device__ __forceinline__ float to_tf32(float x) {
    float r;
    asm("cvt.rna.tf32.f32 %0, %1;" : "=f"(r) : "f"(x));
    return r;
}
__device__ __forceinline__ unsigned ld_rlx(const unsigned* p) {
    unsigned v;
    asm volatile("ld.relaxed.gpu.u32 %0, [%1];" : "=r"(v) : "l"(p) : "memory");
    return v;
}
__device__ __forceinline__ void red_release(unsigned* p) {
    asm volatile("red.release.gpu.global.add.u32 [%0], %1;" :: "l"(p), "r"(1u) : "memory");
}
__device__ __forceinline__ void cpa16(uint32_t dst, const void* src) {
    asm volatile("cp.async.cg.shared.global [%0], [%1], 16;" :: "r"(dst), "l"(src));
}
#define CP_COMMIT() asm volatile("cp.async.commit_group;" ::: "memory")
#define CP_WAIT0()  asm volatile("cp.async.wait_group 0;"  ::: "memory")
#define CP_WAIT1()  asm volatile("cp.async.wait_group 1;"  ::: "memory")

// ---------------- TF32 GEMM for pre0 (from R3, unchanged math) ------------------
__global__ __launch_bounds__(256)
void gemm_tf32(const float* __restrict__ A, const float* __restrict__ W,
               float* __restrict__ out, int K, int sA_t, int sA_b)
{
    extern __shared__ float sm[];
    float* As = sm;
    float* Bs = sm + 2 * GBM * GLD;

    const int tid = threadIdx.x;
    const int wid = tid >> 5;
    const int wm  = wid & 1;
    const int wn  = wid >> 1;
    const int bx  = blockIdx.x;
    const int by  = blockIdx.y;

    const int lRow = tid >> 1;
    const int lC   = (tid & 1) * 16;
    const int r    = by * GBM + lRow;
    const int tt   = r >> 6;
    const int bb   = r & 63;
    const float* aPtr = A + (size_t)bb * sA_b + (size_t)tt * sA_t + lC;
    const float* wPtr = W + (size_t)(bx * GBN + lRow) * K + lC;

    wmma::fragment<wmma::accumulator, 16, 16, 8, float> acc[4][2];
    #pragma unroll
    for (int i = 0; i < 4; i++)
        #pragma unroll
        for (int j = 0; j < 2; j++) wmma::fill_fragment(acc[i][j], 0.0f);

    float4 ra[4], rb[4];
    #pragma unroll
    for (int p = 0; p < 4; p++) {
        ra[p] = *(const float4*)(aPtr + p * 4);
        rb[p] = *(const float4*)(wPtr + p * 4);
    }

    const int niter = K / GBK;
    for (int c = 0; c < niter; c++) {
        {
            float* dA = As + (c & 1) * GBM * GLD + lRow * GLD + lC;
            float* dB = Bs + (c & 1) * GBN * GLD + lRow * GLD + lC;
            #pragma unroll
            for (int p = 0; p < 4; p++) {
                dA[p*4+0] = to_tf32(ra[p].x); dA[p*4+1] = to_tf32(ra[p].y);
                dA[p*4+2] = to_tf32(ra[p].z); dA[p*4+3] = to_tf32(ra[p].w);
                dB[p*4+0] = to_tf32(rb[p].x); dB[p*4+1] = to_tf32(rb[p].y);
                dB[p*4+2] = to_tf32(rb[p].z); dB[p*4+3] = to_tf32(rb[p].w);
            }
        }
        if (c + 1 < niter) {
            const float* a2 = aPtr + (c + 1) * GBK;
            const float* w2 = wPtr + (c + 1) * GBK;
            #pragma unroll
            for (int p = 0; p < 4; p++) {
                ra[p] = *(const float4*)(a2 + p * 4);
                rb[p] = *(const float4*)(w2 + p * 4);
            }
        }
        __syncthreads();

        const float* bufA = As + (c & 1) * GBM * GLD;
        const float* bufB = Bs + (c & 1) * GBN * GLD;
        #pragma unroll
        for (int s = 0; s < 4; s++) {
            wmma::fragment<wmma::matrix_a, 16, 16, 8, wmma::precision::tf32, wmma::row_major> af[4];
            wmma::fragment<wmma::matrix_b, 16, 16, 8, wmma::precision::tf32, wmma::col_major> bf[2];
            #pragma unroll
            for (int i = 0; i < 4; i++)
                wmma::load_matrix_sync(af[i], bufA + (wm * 64 + i * 16) * GLD + s * 8, GLD);
            #pragma unroll
            for (int j = 0; j < 2; j++)
                wmma::load_matrix_sync(bf[j], bufB + (wn * 32 + j * 16) * GLD + s * 8, GLD);
            #pragma unroll
            for (int i = 0; i < 4; i++)
                #pragma unroll
                for (int j = 0; j < 2; j++)
                    wmma::mma_sync(acc[i][j], af[i], bf[j], acc[i][j]);
        }
        __syncthreads();
    }

    #pragma unroll
    for (int i = 0; i < 4; i++)
        #pragma unroll
        for (int j = 0; j < 2; j++) {
            const int rr = by * GBM + wm * 64 + i * 16;
            const int cc = bx * GBN + wn * 32 + j * 16;
            wmma::store_matrix_sync(out + (size_t)rr * RH + cc, acc[i][j], RH, wmma::mem_row_major);
        }
}

// ---------------- fused wavefront recurrence -----------------------------------
// Role template: NC = columns owned per CTA, NMAT = #input matrices (1: hh only,
// 2: ih+hh). h exchanged via fp16 history arrays gated by per-layer counters.
template<int NC, int NMAT>
__device__ __forceinline__ void rec_role(
    int cta, char* smraw,
    const float* __restrict__ pre,                 // fp32 pre (L0) or nullptr (L1)
    const float* __restrict__ WA,                  // W for srcA (hh0 / ih1)
    const float* __restrict__ WB,                  // W for srcB (hh1) or nullptr
    const float* __restrict__ bi, const float* __restrict__ bh,
    const __half* __restrict__ srcA,               // h1 history
    const __half* __restrict__ srcB,               // h2 history (L1) or nullptr
    __half* __restrict__ dst,                      // own history
    const unsigned* cntA, unsigned mulA, int aheadA, int lagA,
    const unsigned* cntB, unsigned mulB,
    unsigned* myCnt)
{
    __half* Ws  = (__half*)smraw;                  // NMAT*NC*LDWs halves (66048 B)
    __half* stg = Ws + NMAT * NC * LDWs;           // 2*RB*LDHs halves   (67584 B)
    float*  rs  = (float*)(stg + 2 * RB * LDHs);   // 2*4*(NC/16)*256 floats
    float*  sb  = rs + 2 * 4 * (NC / 16) * 256;    // NC floats

    const int tid   = threadIdx.x;
    const int wid   = tid >> 5;
    const int mt    = wid >> 1;                    // m-tile (16 batch rows)
    const int ks    = wid & 1;                     // k-split half
    const int ncol0 = cta * NC;

    // resident W slices as fp16
    #pragma unroll 1
    for (int m = 0; m < NMAT; m++) {
        const float* W = m ? WB : WA;
        for (int i = tid; i < NC * RH / 8; i += 256) {
            const int n  = i / (RH / 8);
            const int k8 = i % (RH / 8);
            const float* wp = W + (size_t)(ncol0 + n) * RH + k8 * 8;
            float4 v0 = *(const float4*)(wp);
            float4 v1 = *(const float4*)(wp + 4);
            __half2 h0 = __floats2half2_rn(v0.x, v0.y);
            __half2 h1 = __floats2half2_rn(v0.z, v0.w);
            __half2 h2 = __floats2half2_rn(v1.x, v1.y);
            __half2 h3 = __floats2half2_rn(v1.z, v1.w);
            __half2* d = (__half2*)(Ws + m * NC * LDWs + n * LDWs + k8 * 8);
            d[0] = h0; d[1] = h1; d[2] = h2; d[3] = h3;
        }
    }
    if (tid < NC) sb[tid] = bi[ncol0 + tid] + bh[ncol0 + tid];
    __syncthreads();

    const uint32_t stg_u32 = (uint32_t)__cvta_generic_to_shared(stg);
    const int srow = tid >> 2;                     // 0..63  (batch row staged)
    const int scol = (tid & 3) * 64;               // halves within chunk

    // epilogue geometry
    const int eb   = tid >> 2;
    const int embt = eb >> 4;
    const int ebr  = eb & 15;
    const int en0  = (tid & 3) * (NC / 4);

    #pragma unroll 1
    for (int t = 0; t < RT; ++t) {
        // ---- wait on producers (single poller) ----
        if (tid == 0) {
            if (t + aheadA > 0) {
                const unsigned tgt = mulA * (unsigned)(t + aheadA);
                while (ld_rlx(cntA) < tgt) { }
            }
            if (NMAT == 2 && t > 0) {
                const unsigned tgt = mulB * (unsigned)t;
                while (ld_rlx(cntB) < tgt) { }
            }
            asm volatile("fence.acq_rel.gpu;" ::: "memory");
        }
        __syncthreads();

        wmma::fragment<wmma::accumulator, 16, 16, 16, float> acc[NC / 16];
        #pragma unroll
        for (int i = 0; i < NC / 16; i++) wmma::fill_fragment(acc[i], 0.0f);

        const int nchk = (NMAT == 2) ? (t > 0 ? 8 : 4) : (t > 0 ? 4 : 0);

        if (nchk > 0) {
            // issue chunk 0
            {
                const __half* base = srcA + (size_t)(t - lagA) * BH;
                const __half* s = base + srow * RH + scol;
                const uint32_t d = stg_u32 + (srow * LDHs + scol) * 2;
                #pragma unroll
                for (int j = 0; j < 8; j++) cpa16(d + j * 16, s + j * 8);
                CP_COMMIT();
            }
            #pragma unroll 1
            for (int c = 0; c < nchk; c++) {
                if (c + 1 < nchk) {
                    const int  m2 = (NMAT == 2) ? ((c + 1) >> 2) : 0;
                    const int  ci = (c + 1) & 3;
                    const __half* base = m2 ? (srcB + (size_t)(t - 1) * BH)
                                            : (srcA + (size_t)(t - lagA) * BH);
                    const __half* s = base + srow * RH + ci * KC + scol;
                    const uint32_t d = stg_u32
                        + (((c + 1) & 1) * RB * LDHs + srow * LDHs + scol) * 2;
                    #pragma unroll
                    for (int j = 0; j < 8; j++) cpa16(d + j * 16, s + j * 8);
                    CP_COMMIT();
                    CP_WAIT1();
                } else {
                    CP_WAIT0();
                }
                __syncthreads();

                const __half* buf = stg + (c & 1) * RB * LDHs;
                const __half* Wb  = Ws + ((NMAT == 2) ? (c >> 2) : 0) * NC * LDWs
                                       + (c & 3) * KC;
                #pragma unroll
                for (int s8 = 0; s8 < 8; s8++) {
                    const int k = ks * 128 + s8 * 16;
                    wmma::fragment<wmma::matrix_a, 16, 16, 16, __half, wmma::row_major> af;
                    wmma::load_matrix_sync(af, buf + (mt * 16) * LDHs + k, LDHs);
                    #pragma unroll
                    for (int nt = 0; nt < NC / 16; nt++) {
                        wmma::fragment<wmma::matrix_b, 16, 16, 16, __half, wmma::col_major> bf;
                        wmma::load_matrix_sync(bf, Wb + (nt * 16) * LDWs + k, LDWs);
                        wmma::mma_sync(acc[nt], af, bf, acc[nt]);
                    }
                }
                __syncthreads();
            }
        }

        // ---- k-split reduce + tanh + publish ----
        #pragma unroll
        for (int nt = 0; nt < NC / 16; nt++)
            wmma::store_matrix_sync(rs + ((ks * 4 + mt) * (NC / 16) + nt) * 256,
                                    acc[nt], 16, wmma::mem_row_major);
        __syncthreads();
        {
            __half* drow = dst + (size_t)t * BH + eb * RH + ncol0 + en0;
            const float* prow = pre ? (pre + (size_t)t * BH + eb * RH + ncol0 + en0)
                                    : nullptr;
            #pragma unroll
            for (int j = 0; j < NC / 4; j += 2) {
                float v[2];
                #pragma unroll
                for (int u = 0; u < 2; u++) {
                    const int nl = en0 + j + u;
                    const int nt = nl >> 4;
                    const int nc = nl & 15;
                    float s = rs[((0 * 4 + embt) * (NC / 16) + nt) * 256 + ebr * 16 + nc]
                            + rs[((1 * 4 + embt) * (NC / 16) + nt) * 256 + ebr * 16 + nc]
                            + sb[nl];
                    if (prow) s += prow[j + u];
                    v[u] = tanhf(s);
                }
                *(__half2*)(drow + j) = __floats2half2_rn(v[0], v[1]);
            }
        }
        __syncthreads();
        if (tid == 0) red_release(myCnt);
    }
}

__global__ __launch_bounds__(256)
void rec_fused(const float* __restrict__ pre0,
               const float* __restrict__ Whh0,
               const float* __restrict__ bih0, const float* __restrict__ bhh0,
               const float* __restrict__ Wih1, const float* __restrict__ Whh1,
               const float* __restrict__ bih1, const float* __restrict__ bhh1)
{
    extern __shared__ char smraw[];
    if (blockIdx.x < L0_CTAS) {
        // L0: h1[t] = tanh(pre0[t] + Whh0 h1[t-1] + b); waits own layer cnt >= 32*t
        rec_role<32, 1>(blockIdx.x, smraw, pre0, Whh0, nullptr, bih0, bhh0,
                        g_h1h, nullptr, g_h1h,
                        &g_cnt[0], L0_CTAS, /*aheadA=*/0, /*lagA=*/1,
                        nullptr, 0, &g_cnt[0]);
    } else {
        // L1: h2[t] = tanh(Wih1 h1[t] + Whh1 h2[t-1] + b)
        // waits cntL0 >= 32*(t+1) and cntL1 >= 64*t
        rec_role<16, 2>(blockIdx.x - L0_CTAS, smraw, nullptr, Wih1, Whh1, bih1, bhh1,
                        g_h1h, g_h2h, g_h2h,
                        &g_cnt[0], L0_CTAS, /*aheadA=*/1, /*lagA=*/0,
                        &g_cnt[1], L1_CTAS, &g_cnt[1]);
    }
}

// ---------------- FC head (fp16 h, fp32 W/out) ---------------------------------
__global__ __launch_bounds__(256)
void fc_kernel(const __half* __restrict__ h, const float* __restrict__ Wfc,
               const float* __restrict__ bfc, float* __restrict__ out)
{
    const int w    = (blockIdx.x * blockDim.x + threadIdx.x) >> 5;
    const int lane = threadIdx.x & 31;
    if (w >= RB * RDO) return;
    const int b = w >> 9;
    const int o = w & (RDO - 1);

    const __half* hp = h   + (size_t)b * RH;
    const float*  wp = Wfc + (size_t)o * RH;
    float acc = 0.f;
    #pragma unroll
    for (int k = lane * 8; k < RH; k += 256) {
        const __half2* hv = (const __half2*)(hp + k);
        #pragma unroll
        for (int q = 0; q < 4; q++) {
            float2 hf = __half22float2(hv[q]);
            acc += hf.x * wp[k + q * 2] + hf.y * wp[k + q * 2 + 1];
        }
    }
    #pragma unroll
    for (int s = 16; s > 0; s >>= 1) acc += __shfl_xor_sync(0xffffffffu, acc, s);
    if (lane == 0) out[w] = acc + bfc[o];
}

// ---------------- launch -------------------------------------------------------
extern "C" void kernel_launch(void* const* d_in, const int* in_sizes, int n_in,
                              void* d_out, int out_size)
{
    const float* x     = (const float*)d_in[0];
    const float* W_ih0 = (const float*)d_in[1];
    const float* W_hh0 = (const float*)d_in[2];
    const float* b_ih0 = (const float*)d_in[3];
    const float* b_hh0 = (const float*)d_in[4];
    const float* W_ih1 = (const float*)d_in[5];
    const float* W_hh1 = (const float*)d_in[6];
    const float* b_ih1 = (const float*)d_in[7];
    const float* b_hh1 = (const float*)d_in[8];
    const float* W_fc  = (const float*)d_in[9];
    const float* b_fc  = (const float*)d_in[10];

    float*  pre;
    __half* h2;
    unsigned* cnt;
    cudaGetSymbolAddress((void**)&pre, g_pre);
    cudaGetSymbolAddress((void**)&h2,  g_h2h);
    cudaGetSymbolAddress((void**)&cnt, g_cnt);

    cudaFuncSetAttribute(gemm_tf32, cudaFuncAttributeMaxDynamicSharedMemorySize, GEMM_SMEM_BYTES);
    cudaFuncSetAttribute(rec_fused, cudaFuncAttributeMaxDynamicSharedMemorySize, REC_SMEM_BYTES);

    cudaMemsetAsync(cnt, 0, 2 * sizeof(unsigned), 0);

    // pre0 = x @ W_ih0^T   (x[b][t][d]: sA_t = RDI, sA_b = RT*RDI)
    dim3 ggrid(RH / GBN, (RT * RB) / GBM);
    gemm_tf32<<<ggrid, 256, GEMM_SMEM_BYTES>>>(x, W_ih0, pre, RDI, RDI, RT * RDI);

    // fused two-layer wavefront recurrence
    rec_fused<<<L0_CTAS + L1_CTAS, 256, REC_SMEM_BYTES>>>(
        pre, W_hh0, b_ih0, b_hh0, W_ih1, W_hh1, b_ih1, b_hh1);

    // FC head on final layer-1 state
    fc_kernel<<<(RB * RDO) / 8, 256>>>(h2 + (size_t)(RT - 1) * BH,
                                       W_fc, b_fc, (float*)d_out);
}